// round 1
// baseline (speedup 1.0000x reference)
#include <cuda_runtime.h>
#include <math.h>

#define N_NODES 8192
#define D 256
#define MAXNNZ 128   // nnz/row ~ Binomial(8192, 32/8192): mean 32, std 5.7 -> 128 is ~17 sigma

// Scratch: ELL adjacency (4 matrices) + 8 feature buffers [8192,256] fp32
__device__ int   g_cols[4][N_NODES * MAXNNZ];
__device__ int   g_len[4][N_NODES];
__device__ float g_buf[8][N_NODES * D];

// ---------------------------------------------------------------------------
// Extract binary adjacency -> ELL. One warp per row, ballot compaction.
// Order of indices within a row is irrelevant (summation is commutative).
// ---------------------------------------------------------------------------
__global__ void extract_kernel(const float* __restrict__ a0,
                               const float* __restrict__ a1,
                               const float* __restrict__ a2,
                               const float* __restrict__ a3)
{
    int gw   = (blockIdx.x * blockDim.x + threadIdx.x) >> 5;
    int lane = threadIdx.x & 31;
    int mat  = gw >> 13;              // 8192 rows per matrix
    int row  = gw & (N_NODES - 1);
    const float* A = (mat == 0) ? a0 : (mat == 1) ? a1 : (mat == 2) ? a2 : a3;
    const float* arow = A + (size_t)row * N_NODES;
    int* cols = &g_cols[mat][row * MAXNNZ];
    int base = 0;
    for (int c0 = 0; c0 < N_NODES; c0 += 128) {
        float4 v = *(const float4*)(arow + c0 + lane * 4);
        float vv[4] = {v.x, v.y, v.z, v.w};
        #pragma unroll
        for (int j = 0; j < 4; j++) {
            bool nz = (vv[j] != 0.0f);
            unsigned m = __ballot_sync(0xffffffffu, nz);
            if (nz) {
                int off = base + __popc(m & ((1u << lane) - 1u));
                if (off < MAXNNZ) cols[off] = c0 + lane * 4 + j;
            }
            base += __popc(m);
        }
    }
    if (lane == 0) g_len[mat][row] = base < MAXNNZ ? base : MAXNNZ;
}

// ---------------------------------------------------------------------------
// C[8192,256] = X[8192,K] @ W[256,K]^T + bias.  fp32 SIMT tiled.
// 64x64 block tile, BK=16, 256 threads, 4x4 per thread.
// ---------------------------------------------------------------------------
__global__ void gemm_bias_kernel(const float* __restrict__ X,
                                 const float* __restrict__ W,
                                 const float* __restrict__ bias,
                                 float* __restrict__ C, int K)
{
    __shared__ float As[16][68];   // [k][m], padded stride 68 keeps float4 alignment
    __shared__ float Bs[16][68];   // [k][n]
    int tid = threadIdx.x;
    int m0 = blockIdx.y * 64;
    int n0 = blockIdx.x * 64;
    int tx = tid & 15, ty = tid >> 4;
    int lm = tid >> 2;             // 0..63
    int lk = (tid & 3) * 4;        // 0,4,8,12
    const float* Xp = X + (size_t)(m0 + lm) * K + lk;
    const float* Wp = W + (size_t)(n0 + lm) * K + lk;
    float acc[4][4] = {};
    for (int k0 = 0; k0 < K; k0 += 16) {
        float4 xa = *(const float4*)(Xp + k0);
        float4 wb = *(const float4*)(Wp + k0);
        As[lk + 0][lm] = xa.x; As[lk + 1][lm] = xa.y;
        As[lk + 2][lm] = xa.z; As[lk + 3][lm] = xa.w;
        Bs[lk + 0][lm] = wb.x; Bs[lk + 1][lm] = wb.y;
        Bs[lk + 2][lm] = wb.z; Bs[lk + 3][lm] = wb.w;
        __syncthreads();
        #pragma unroll
        for (int k = 0; k < 16; k++) {
            float a[4], b[4];
            #pragma unroll
            for (int i = 0; i < 4; i++) a[i] = As[k][ty * 4 + i];
            #pragma unroll
            for (int j = 0; j < 4; j++) b[j] = Bs[k][tx * 4 + j];
            #pragma unroll
            for (int i = 0; i < 4; i++)
                #pragma unroll
                for (int j = 0; j < 4; j++)
                    acc[i][j] += a[i] * b[j];
        }
        __syncthreads();
    }
    float4 bb = *(const float4*)(bias + n0 + tx * 4);
    float bv[4] = {bb.x, bb.y, bb.z, bb.w};
    #pragma unroll
    for (int i = 0; i < 4; i++) {
        float4 o;
        o.x = acc[i][0] + bv[0];
        o.y = acc[i][1] + bv[1];
        o.z = acc[i][2] + bv[2];
        o.w = acc[i][3] + bv[3];
        *(float4*)(C + (size_t)(m0 + ty * 4 + i) * D + n0 + tx * 4) = o;
    }
}

// ---------------------------------------------------------------------------
// out[row,:] = act( P[row,:] + sum_{c in listA} XA[c,:] + sum_{c in listB} XB[c,:] )
// Optional fused row L2-normalization for the final layer.
// One block per row, 256 threads = one per output column.
// ---------------------------------------------------------------------------
__global__ void combine_kernel(const float* __restrict__ P,
                               const float* __restrict__ XA,
                               const float* __restrict__ XB,
                               int matA, int matB,
                               float* __restrict__ out,
                               int do_norm)
{
    int row = blockIdx.x;
    int tid = threadIdx.x;
    __shared__ int scols[2 * MAXNNZ];
    __shared__ float red[256];
    int lenA = g_len[matA][row];
    int lenB = g_len[matB][row];
    if (tid < MAXNNZ) {
        if (tid < lenA) scols[tid] = g_cols[matA][row * MAXNNZ + tid];
    } else {
        int t = tid - MAXNNZ;
        if (t < lenB) scols[MAXNNZ + t] = g_cols[matB][row * MAXNNZ + t];
    }
    __syncthreads();
    float acc = P[(size_t)row * D + tid];
    #pragma unroll 4
    for (int i = 0; i < lenA; i++)
        acc += XA[(size_t)scols[i] * D + tid];
    #pragma unroll 4
    for (int i = 0; i < lenB; i++)
        acc += XB[(size_t)scols[MAXNNZ + i] * D + tid];
    acc = acc > 0.0f ? acc : 0.1f * acc;      // leaky_relu(., 0.1)
    if (do_norm) {
        red[tid] = acc * acc;
        __syncthreads();
        #pragma unroll
        for (int s = 128; s > 0; s >>= 1) {
            if (tid < s) red[tid] += red[tid + s];
            __syncthreads();
        }
        acc = acc / (sqrtf(red[0]) + 1e-9f);
    }
    out[(size_t)row * D + tid] = acc;
}

// ---------------------------------------------------------------------------
// Launch: ELL extract -> 6 GEMMs -> 2 combines -> 6 GEMMs -> 2 combines+norm
// ---------------------------------------------------------------------------
extern "C" void kernel_launch(void* const* d_in, const int* in_sizes, int n_in,
                              void* d_out, int out_size)
{
    const float* hp         = (const float*)d_in[0];
    const float* hq         = (const float*)d_in[1];
    const float* a_cons     = (const float*)d_in[2];
    const float* a_prod     = (const float*)d_in[3];
    const float* a_rev_cons = (const float*)d_in[4];
    const float* a_rev_prod = (const float*)d_in[5];
    // weights: 0 wp1, 1 wq1, 2 wcons1, 3 wrprod1, 4 wprod1, 5 wrcons1,
    //          6 wp2, 7 wq2, 8 wcons2, 9 wrprod2, 10 wprod2, 11 wrcons2
    const float* w[12];
    const float* b[12];
    for (int i = 0; i < 12; i++) {
        w[i] = (const float*)d_in[6 + 2 * i];
        b[i] = (const float*)d_in[7 + 2 * i];
    }
    float* out = (float*)d_out;

    void* symp = nullptr;
    cudaGetSymbolAddress(&symp, g_buf);
    float* B0 = (float*)symp;
    #define BUF(i) (B0 + (size_t)(i) * N_NODES * D)

    // adjacency ELL: mat ids 0=a_cons, 1=a_prod, 2=a_rev_cons, 3=a_rev_prod
    extract_kernel<<<4 * N_NODES / 8, 256>>>(a_cons, a_prod, a_rev_cons, a_rev_prod);

    dim3 gg(D / 64, N_NODES / 64), gb(256);
    // ---- layer 1 (K = 512) ----
    gemm_bias_kernel<<<gg, gb>>>(hp, w[0],  b[0],  BUF(0), 512);  // Pp   = lin(hp, wp1)
    gemm_bias_kernel<<<gg, gb>>>(hq, w[1],  b[1],  BUF(1), 512);  // Pq   = lin(hq, wq1)
    gemm_bias_kernel<<<gg, gb>>>(hq, w[2],  b[2],  BUF(2), 512);  // Xc   = lin(hq, wcons1)
    gemm_bias_kernel<<<gg, gb>>>(hq, w[3],  b[3],  BUF(3), 512);  // Xrp  = lin(hq, wrprod1)
    gemm_bias_kernel<<<gg, gb>>>(hp, w[4],  b[4],  BUF(4), 512);  // Xp   = lin(hp, wprod1)
    gemm_bias_kernel<<<gg, gb>>>(hp, w[5],  b[5],  BUF(5), 512);  // Xrc  = lin(hp, wrcons1)
    combine_kernel<<<N_NODES, 256>>>(BUF(0), BUF(2), BUF(3), 0, 3, BUF(6), 0);  // hp1
    combine_kernel<<<N_NODES, 256>>>(BUF(1), BUF(4), BUF(5), 1, 2, BUF(7), 0);  // hq1
    // ---- layer 2 (K = 256) ----
    gemm_bias_kernel<<<gg, gb>>>(BUF(6), w[6],  b[6],  BUF(0), 256);  // lin(hp1, wp2)
    gemm_bias_kernel<<<gg, gb>>>(BUF(7), w[7],  b[7],  BUF(1), 256);  // lin(hq1, wq2)
    gemm_bias_kernel<<<gg, gb>>>(BUF(7), w[8],  b[8],  BUF(2), 256);  // lin(hq1, wcons2)
    gemm_bias_kernel<<<gg, gb>>>(BUF(7), w[9],  b[9],  BUF(3), 256);  // lin(hq1, wrprod2)
    gemm_bias_kernel<<<gg, gb>>>(BUF(6), w[10], b[10], BUF(4), 256);  // lin(hp1, wprod2)
    gemm_bias_kernel<<<gg, gb>>>(BUF(6), w[11], b[11], BUF(5), 256);  // lin(hp1, wrcons2)
    combine_kernel<<<N_NODES, 256>>>(BUF(0), BUF(2), BUF(3), 0, 3, out, 1);                         // norm(hp2)
    combine_kernel<<<N_NODES, 256>>>(BUF(1), BUF(4), BUF(5), 1, 2, out + (size_t)N_NODES * D, 1);   // norm(hq2)
    #undef BUF
}

// round 3
// speedup vs baseline: 1.7505x; 1.7505x over previous
#include <cuda_runtime.h>
#include <math.h>

#define N_NODES 8192
#define D 256
#define MAXNNZ 128

// Scratch: ELL adjacency (4 matrices) + 8 feature buffers [8192,256] fp32
__device__ int   g_cols[4][N_NODES * MAXNNZ];
__device__ int   g_len[4][N_NODES];
__device__ float g_buf[8][N_NODES * D];

// ---------------------------------------------------------------------------
// Extract binary adjacency -> ELL. One warp per row, ballot compaction.
// ---------------------------------------------------------------------------
__global__ void extract_kernel(const float* __restrict__ a0,
                               const float* __restrict__ a1,
                               const float* __restrict__ a2,
                               const float* __restrict__ a3)
{
    int gw   = (blockIdx.x * blockDim.x + threadIdx.x) >> 5;
    int lane = threadIdx.x & 31;
    int mat  = gw >> 13;
    int row  = gw & (N_NODES - 1);
    const float* A = (mat == 0) ? a0 : (mat == 1) ? a1 : (mat == 2) ? a2 : a3;
    const float* arow = A + (size_t)row * N_NODES;
    int* cols = &g_cols[mat][row * MAXNNZ];
    int base = 0;
    for (int c0 = 0; c0 < N_NODES; c0 += 128) {
        float4 v = *(const float4*)(arow + c0 + lane * 4);
        float vv[4] = {v.x, v.y, v.z, v.w};
        #pragma unroll
        for (int j = 0; j < 4; j++) {
            bool nz = (vv[j] != 0.0f);
            unsigned m = __ballot_sync(0xffffffffu, nz);
            if (nz) {
                int off = base + __popc(m & ((1u << lane) - 1u));
                if (off < MAXNNZ) cols[off] = c0 + lane * 4 + j;
            }
            base += __popc(m);
        }
    }
    if (lane == 0) g_len[mat][row] = base < MAXNNZ ? base : MAXNNZ;
}

// ---------------------------------------------------------------------------
// Fused 3-in-1 tf32 tensor-core GEMM.
// For one shared input X[8192,K], computes Ci = X @ Wi^T + bi  (i=0..2),
// each Wi [256,K], Ci [8192,256].
// grid = (6, 64): blockIdx.x -> (mat = x>>1, n0 = (x&1)*128); blockIdx.y -> m0.
// Block tile 128x128, BK=16 double-buffered. 8 warps, each 32(M)x64(N) via
// m16n8k8 tf32 mma (2 m-tiles x 8 n-tiles). Smem row stride 20 floats =
// conflict-free fragment loads (20*g mod 32 distinct for g=0..7).
// ---------------------------------------------------------------------------
__device__ __forceinline__ unsigned f2tf32(float f) {
    unsigned r;
    asm("cvt.rna.tf32.f32 %0, %1;" : "=r"(r) : "f"(f));
    return r;
}

__device__ __forceinline__ void mma_tf32(float* c, const unsigned* a, const unsigned* b) {
    asm volatile(
        "mma.sync.aligned.m16n8k8.row.col.f32.tf32.tf32.f32 "
        "{%0,%1,%2,%3}, {%4,%5,%6,%7}, {%8,%9}, {%0,%1,%2,%3};"
        : "+f"(c[0]), "+f"(c[1]), "+f"(c[2]), "+f"(c[3])
        : "r"(a[0]), "r"(a[1]), "r"(a[2]), "r"(a[3]), "r"(b[0]), "r"(b[1]));
}

#define SST 20   // smem row stride (floats)

__global__ void __launch_bounds__(256) gemm3_mma(
    const float* __restrict__ X,
    const float* __restrict__ W0, const float* __restrict__ W1, const float* __restrict__ W2,
    const float* __restrict__ b0, const float* __restrict__ b1, const float* __restrict__ b2,
    float* __restrict__ C0, float* __restrict__ C1, float* __restrict__ C2, int K)
{
    __shared__ float As[2][128 * SST];
    __shared__ float Bs[2][128 * SST];

    int tid  = threadIdx.x;
    int nblk = blockIdx.x;
    int mat  = nblk >> 1;
    int n0   = (nblk & 1) * 128;
    int m0   = blockIdx.y * 128;

    const float* W    = (mat == 0) ? W0 : (mat == 1) ? W1 : W2;
    const float* bias = (mat == 0) ? b0 : (mat == 1) ? b1 : b2;
    float*       C    = (mat == 0) ? C0 : (mat == 1) ? C1 : C2;

    int wid = tid >> 5, lane = tid & 31;
    int wm = (wid >> 1) * 32;      // warp M offset (0,32,64,96)
    int wn = (wid & 1) * 64;       // warp N offset (0,64)
    int gid = lane >> 2;           // 0..7
    int tg  = lane & 3;            // 0..3

    float acc[2][8][4];
    #pragma unroll
    for (int i = 0; i < 2; i++)
        #pragma unroll
        for (int j = 0; j < 8; j++)
            #pragma unroll
            for (int k = 0; k < 4; k++) acc[i][j][k] = 0.0f;

    int lrow = tid >> 2;           // 0..63
    int lc4  = (tid & 3) * 4;      // 0,4,8,12

    int nkc = K >> 4;
    float4 xv[2], wv[2];

    // prologue: load + store chunk 0
    #pragma unroll
    for (int i = 0; i < 2; i++) {
        int r = i * 64 + lrow;
        xv[i] = *(const float4*)(X + (size_t)(m0 + r) * K + lc4);
        wv[i] = *(const float4*)(W + (size_t)(n0 + r) * K + lc4);
    }
    #pragma unroll
    for (int i = 0; i < 2; i++) {
        int base = (i * 64 + lrow) * SST + lc4;
        As[0][base + 0] = __uint_as_float(f2tf32(xv[i].x));
        As[0][base + 1] = __uint_as_float(f2tf32(xv[i].y));
        As[0][base + 2] = __uint_as_float(f2tf32(xv[i].z));
        As[0][base + 3] = __uint_as_float(f2tf32(xv[i].w));
        Bs[0][base + 0] = __uint_as_float(f2tf32(wv[i].x));
        Bs[0][base + 1] = __uint_as_float(f2tf32(wv[i].y));
        Bs[0][base + 2] = __uint_as_float(f2tf32(wv[i].z));
        Bs[0][base + 3] = __uint_as_float(f2tf32(wv[i].w));
    }
    __syncthreads();

    for (int kc = 0; kc < nkc; kc++) {
        int buf = kc & 1;
        bool more = (kc + 1) < nkc;
        if (more) {
            int koff = (kc + 1) * 16;
            #pragma unroll
            for (int i = 0; i < 2; i++) {
                int r = i * 64 + lrow;
                xv[i] = *(const float4*)(X + (size_t)(m0 + r) * K + koff + lc4);
                wv[i] = *(const float4*)(W + (size_t)(n0 + r) * K + koff + lc4);
            }
        }
        // compute: two k8 steps on this buffer
        #pragma unroll
        for (int k8 = 0; k8 < 16; k8 += 8) {
            unsigned a[2][4];
            #pragma unroll
            for (int mt = 0; mt < 2; mt++) {
                int r = wm + mt * 16 + gid;
                a[mt][0] = __float_as_uint(As[buf][(r)     * SST + k8 + tg]);
                a[mt][1] = __float_as_uint(As[buf][(r + 8) * SST + k8 + tg]);
                a[mt][2] = __float_as_uint(As[buf][(r)     * SST + k8 + tg + 4]);
                a[mt][3] = __float_as_uint(As[buf][(r + 8) * SST + k8 + tg + 4]);
            }
            #pragma unroll
            for (int nt = 0; nt < 8; nt++) {
                int rn = wn + nt * 8 + gid;
                unsigned b[2];
                b[0] = __float_as_uint(Bs[buf][rn * SST + k8 + tg]);
                b[1] = __float_as_uint(Bs[buf][rn * SST + k8 + tg + 4]);
                mma_tf32(acc[0][nt], a[0], b);
                mma_tf32(acc[1][nt], a[1], b);
            }
        }
        __syncthreads();
        if (more) {
            int ob = buf ^ 1;
            #pragma unroll
            for (int i = 0; i < 2; i++) {
                int base = (i * 64 + lrow) * SST + lc4;
                As[ob][base + 0] = __uint_as_float(f2tf32(xv[i].x));
                As[ob][base + 1] = __uint_as_float(f2tf32(xv[i].y));
                As[ob][base + 2] = __uint_as_float(f2tf32(xv[i].z));
                As[ob][base + 3] = __uint_as_float(f2tf32(xv[i].w));
                Bs[ob][base + 0] = __uint_as_float(f2tf32(wv[i].x));
                Bs[ob][base + 1] = __uint_as_float(f2tf32(wv[i].y));
                Bs[ob][base + 2] = __uint_as_float(f2tf32(wv[i].z));
                Bs[ob][base + 3] = __uint_as_float(f2tf32(wv[i].w));
            }
            __syncthreads();
        }
    }

    // epilogue: add bias, store
    #pragma unroll
    for (int mt = 0; mt < 2; mt++) {
        #pragma unroll
        for (int nt = 0; nt < 8; nt++) {
            int col = n0 + wn + nt * 8 + tg * 2;
            float2 bv = *(const float2*)(bias + col);
            int r0 = m0 + wm + mt * 16 + gid;
            float2 o0 = {acc[mt][nt][0] + bv.x, acc[mt][nt][1] + bv.y};
            float2 o1 = {acc[mt][nt][2] + bv.x, acc[mt][nt][3] + bv.y};
            *(float2*)(C + (size_t)r0 * D + col)       = o0;
            *(float2*)(C + (size_t)(r0 + 8) * D + col) = o1;
        }
    }
}

// ---------------------------------------------------------------------------
// out[row,:] = act( P[row,:] + sum_{c in A} XA[c,:] + sum_{c in B} XB[c,:] )
// Optional fused row L2-norm. One block per row, 256 threads = one per column.
// ---------------------------------------------------------------------------
__global__ void combine_kernel(const float* __restrict__ P,
                               const float* __restrict__ XA,
                               const float* __restrict__ XB,
                               int matA, int matB,
                               float* __restrict__ out,
                               int do_norm)
{
    int row = blockIdx.x;
    int tid = threadIdx.x;
    __shared__ int scols[2 * MAXNNZ];
    __shared__ float red[256];
    int lenA = g_len[matA][row];
    int lenB = g_len[matB][row];
    if (tid < MAXNNZ) {
        if (tid < lenA) scols[tid] = g_cols[matA][row * MAXNNZ + tid];
    } else {
        int t = tid - MAXNNZ;
        if (t < lenB) scols[MAXNNZ + t] = g_cols[matB][row * MAXNNZ + t];
    }
    __syncthreads();
    float acc = P[(size_t)row * D + tid];
    #pragma unroll 4
    for (int i = 0; i < lenA; i++)
        acc += XA[(size_t)scols[i] * D + tid];
    #pragma unroll 4
    for (int i = 0; i < lenB; i++)
        acc += XB[(size_t)scols[MAXNNZ + i] * D + tid];
    acc = acc > 0.0f ? acc : 0.1f * acc;
    if (do_norm) {
        red[tid] = acc * acc;
        __syncthreads();
        #pragma unroll
        for (int s = 128; s > 0; s >>= 1) {
            if (tid < s) red[tid] += red[tid + s];
            __syncthreads();
        }
        acc = acc / (sqrtf(red[0]) + 1e-9f);
    }
    out[(size_t)row * D + tid] = acc;
}

// ---------------------------------------------------------------------------
extern "C" void kernel_launch(void* const* d_in, const int* in_sizes, int n_in,
                              void* d_out, int out_size)
{
    const float* hp         = (const float*)d_in[0];
    const float* hq         = (const float*)d_in[1];
    const float* a_cons     = (const float*)d_in[2];
    const float* a_prod     = (const float*)d_in[3];
    const float* a_rev_cons = (const float*)d_in[4];
    const float* a_rev_prod = (const float*)d_in[5];
    const float* w[12];
    const float* b[12];
    for (int i = 0; i < 12; i++) {
        w[i] = (const float*)d_in[6 + 2 * i];
        b[i] = (const float*)d_in[7 + 2 * i];
    }
    float* out = (float*)d_out;

    void* symp = nullptr;
    cudaGetSymbolAddress(&symp, g_buf);
    float* B0 = (float*)symp;
    #define BUF(i) (B0 + (size_t)(i) * N_NODES * D)

    // adjacency ELL: 0=a_cons, 1=a_prod, 2=a_rev_cons, 3=a_rev_prod
    extract_kernel<<<4 * N_NODES / 8, 256>>>(a_cons, a_prod, a_rev_cons, a_rev_prod);

    dim3 gg(6, N_NODES / 128), gb(256);
    // ---- layer 1 (K = 512) ----
    // P-side: X=hp -> {wp1->BUF0, wprod1->BUF4, wrcons1->BUF5}
    gemm3_mma<<<gg, gb>>>(hp, w[0], w[4], w[5], b[0], b[4], b[5],
                          BUF(0), BUF(4), BUF(5), 512);
    // Q-side: X=hq -> {wq1->BUF1, wcons1->BUF2, wrprod1->BUF3}
    gemm3_mma<<<gg, gb>>>(hq, w[1], w[2], w[3], b[1], b[2], b[3],
                          BUF(1), BUF(2), BUF(3), 512);
    combine_kernel<<<N_NODES, 256>>>(BUF(0), BUF(2), BUF(3), 0, 3, BUF(6), 0);  // hp1
    combine_kernel<<<N_NODES, 256>>>(BUF(1), BUF(4), BUF(5), 1, 2, BUF(7), 0);  // hq1
    // ---- layer 2 (K = 256) ----
    // P-side: X=hp1 -> {wp2->BUF0, wprod2->BUF4, wrcons2->BUF5}
    gemm3_mma<<<gg, gb>>>(BUF(6), w[6], w[10], w[11], b[6], b[10], b[11],
                          BUF(0), BUF(4), BUF(5), 256);
    // Q-side: X=hq1 -> {wq2->BUF1, wcons2->BUF2, wrprod2->BUF3}
    gemm3_mma<<<gg, gb>>>(BUF(7), w[7], w[8], w[9], b[7], b[8], b[9],
                          BUF(1), BUF(2), BUF(3), 256);
    combine_kernel<<<N_NODES, 256>>>(BUF(0), BUF(2), BUF(3), 0, 3, out, 1);
    combine_kernel<<<N_NODES, 256>>>(BUF(1), BUF(4), BUF(5), 1, 2, out + (size_t)N_NODES * D, 1);
    #undef BUF
}

// round 4
// speedup vs baseline: 2.0734x; 1.1845x over previous
#include <cuda_runtime.h>
#include <math.h>

#define N_NODES 8192
#define D 256
#define MAXNNZ 128

// Scratch: ELL adjacency (4 matrices) + 8 feature buffers [8192,256] fp32
__device__ int   g_cols[4][N_NODES * MAXNNZ];
__device__ int   g_len[4][N_NODES];
__device__ float g_buf[8][N_NODES * D];

// Side stream + events for overlapping extract with layer-1 GEMMs.
// Created once at load time (no device-memory allocation involved).
static cudaStream_t g_s2 = nullptr;
static cudaEvent_t  g_evF = nullptr, g_evJ = nullptr;
static int g_sinit = []() {
    if (cudaStreamCreateWithFlags(&g_s2, cudaStreamNonBlocking) != cudaSuccess) { g_s2 = nullptr; return 0; }
    if (cudaEventCreateWithFlags(&g_evF, cudaEventDisableTiming) != cudaSuccess) { g_s2 = nullptr; return 0; }
    if (cudaEventCreateWithFlags(&g_evJ, cudaEventDisableTiming) != cudaSuccess) { g_s2 = nullptr; return 0; }
    return 1;
}();

// ---------------------------------------------------------------------------
// Extract binary adjacency -> ELL. One warp per row, ballot compaction.
// ---------------------------------------------------------------------------
__global__ void extract_kernel(const float* __restrict__ a0,
                               const float* __restrict__ a1,
                               const float* __restrict__ a2,
                               const float* __restrict__ a3)
{
    int gw   = (blockIdx.x * blockDim.x + threadIdx.x) >> 5;
    int lane = threadIdx.x & 31;
    int mat  = gw >> 13;
    int row  = gw & (N_NODES - 1);
    const float* A = (mat == 0) ? a0 : (mat == 1) ? a1 : (mat == 2) ? a2 : a3;
    const float* arow = A + (size_t)row * N_NODES;
    int* cols = &g_cols[mat][row * MAXNNZ];
    int base = 0;
    for (int c0 = 0; c0 < N_NODES; c0 += 128) {
        float4 v = *(const float4*)(arow + c0 + lane * 4);
        float vv[4] = {v.x, v.y, v.z, v.w};
        #pragma unroll
        for (int j = 0; j < 4; j++) {
            bool nz = (vv[j] != 0.0f);
            unsigned m = __ballot_sync(0xffffffffu, nz);
            if (nz) {
                int off = base + __popc(m & ((1u << lane) - 1u));
                if (off < MAXNNZ) cols[off] = c0 + lane * 4 + j;
            }
            base += __popc(m);
        }
    }
    if (lane == 0) g_len[mat][row] = base < MAXNNZ ? base : MAXNNZ;
}

// ---------------------------------------------------------------------------
// Fused 6-in-1 tf32 tensor-core GEMM (both node types in one launch).
// mats 0..2 use X0, mats 3..5 use X1. Each: Ci = X @ Wi^T + bi.
// grid = (12, 64): blockIdx.x -> (mat = x>>1, n0 = (x&1)*128); blockIdx.y -> m0.
// Block tile 128x128, BK=16 double-buffered, 8 warps x (32x64) m16n8k8 tf32.
// Smem row stride 20 floats: conflict-free fragment loads.
// ---------------------------------------------------------------------------
__device__ __forceinline__ unsigned f2tf32(float f) {
    unsigned r;
    asm("cvt.rna.tf32.f32 %0, %1;" : "=r"(r) : "f"(f));
    return r;
}

__device__ __forceinline__ void mma_tf32(float* c, const unsigned* a, const unsigned* b) {
    asm volatile(
        "mma.sync.aligned.m16n8k8.row.col.f32.tf32.tf32.f32 "
        "{%0,%1,%2,%3}, {%4,%5,%6,%7}, {%8,%9}, {%0,%1,%2,%3};"
        : "+f"(c[0]), "+f"(c[1]), "+f"(c[2]), "+f"(c[3])
        : "r"(a[0]), "r"(a[1]), "r"(a[2]), "r"(a[3]), "r"(b[0]), "r"(b[1]));
}

#define SST 20   // smem row stride (floats)

__global__ void __launch_bounds__(256) gemm6_mma(
    const float* __restrict__ X0, const float* __restrict__ X1,
    const float* __restrict__ W0, const float* __restrict__ W1, const float* __restrict__ W2,
    const float* __restrict__ W3, const float* __restrict__ W4, const float* __restrict__ W5,
    const float* __restrict__ b0, const float* __restrict__ b1, const float* __restrict__ b2,
    const float* __restrict__ b3, const float* __restrict__ b4, const float* __restrict__ b5,
    float* __restrict__ C0, float* __restrict__ C1, float* __restrict__ C2,
    float* __restrict__ C3, float* __restrict__ C4, float* __restrict__ C5, int K)
{
    __shared__ float As[2][128 * SST];
    __shared__ float Bs[2][128 * SST];

    int tid  = threadIdx.x;
    int nblk = blockIdx.x;
    int mat  = nblk >> 1;
    int n0   = (nblk & 1) * 128;
    int m0   = blockIdx.y * 128;

    const float* X = (mat < 3) ? X0 : X1;
    const float* W = (mat == 0) ? W0 : (mat == 1) ? W1 : (mat == 2) ? W2 :
                     (mat == 3) ? W3 : (mat == 4) ? W4 : W5;
    const float* bias = (mat == 0) ? b0 : (mat == 1) ? b1 : (mat == 2) ? b2 :
                        (mat == 3) ? b3 : (mat == 4) ? b4 : b5;
    float* C = (mat == 0) ? C0 : (mat == 1) ? C1 : (mat == 2) ? C2 :
               (mat == 3) ? C3 : (mat == 4) ? C4 : C5;

    int wid = tid >> 5, lane = tid & 31;
    int wm = (wid >> 1) * 32;
    int wn = (wid & 1) * 64;
    int gid = lane >> 2;
    int tg  = lane & 3;

    float acc[2][8][4];
    #pragma unroll
    for (int i = 0; i < 2; i++)
        #pragma unroll
        for (int j = 0; j < 8; j++)
            #pragma unroll
            for (int k = 0; k < 4; k++) acc[i][j][k] = 0.0f;

    int lrow = tid >> 2;
    int lc4  = (tid & 3) * 4;

    int nkc = K >> 4;
    float4 xv[2], wv[2];

    #pragma unroll
    for (int i = 0; i < 2; i++) {
        int r = i * 64 + lrow;
        xv[i] = *(const float4*)(X + (size_t)(m0 + r) * K + lc4);
        wv[i] = *(const float4*)(W + (size_t)(n0 + r) * K + lc4);
    }
    #pragma unroll
    for (int i = 0; i < 2; i++) {
        int base = (i * 64 + lrow) * SST + lc4;
        As[0][base + 0] = __uint_as_float(f2tf32(xv[i].x));
        As[0][base + 1] = __uint_as_float(f2tf32(xv[i].y));
        As[0][base + 2] = __uint_as_float(f2tf32(xv[i].z));
        As[0][base + 3] = __uint_as_float(f2tf32(xv[i].w));
        Bs[0][base + 0] = __uint_as_float(f2tf32(wv[i].x));
        Bs[0][base + 1] = __uint_as_float(f2tf32(wv[i].y));
        Bs[0][base + 2] = __uint_as_float(f2tf32(wv[i].z));
        Bs[0][base + 3] = __uint_as_float(f2tf32(wv[i].w));
    }
    __syncthreads();

    for (int kc = 0; kc < nkc; kc++) {
        int buf = kc & 1;
        bool more = (kc + 1) < nkc;
        if (more) {
            int koff = (kc + 1) * 16;
            #pragma unroll
            for (int i = 0; i < 2; i++) {
                int r = i * 64 + lrow;
                xv[i] = *(const float4*)(X + (size_t)(m0 + r) * K + koff + lc4);
                wv[i] = *(const float4*)(W + (size_t)(n0 + r) * K + koff + lc4);
            }
        }
        #pragma unroll
        for (int k8 = 0; k8 < 16; k8 += 8) {
            unsigned a[2][4];
            #pragma unroll
            for (int mt = 0; mt < 2; mt++) {
                int r = wm + mt * 16 + gid;
                a[mt][0] = __float_as_uint(As[buf][(r)     * SST + k8 + tg]);
                a[mt][1] = __float_as_uint(As[buf][(r + 8) * SST + k8 + tg]);
                a[mt][2] = __float_as_uint(As[buf][(r)     * SST + k8 + tg + 4]);
                a[mt][3] = __float_as_uint(As[buf][(r + 8) * SST + k8 + tg + 4]);
            }
            #pragma unroll
            for (int nt = 0; nt < 8; nt++) {
                int rn = wn + nt * 8 + gid;
                unsigned b[2];
                b[0] = __float_as_uint(Bs[buf][rn * SST + k8 + tg]);
                b[1] = __float_as_uint(Bs[buf][rn * SST + k8 + tg + 4]);
                mma_tf32(acc[0][nt], a[0], b);
                mma_tf32(acc[1][nt], a[1], b);
            }
        }
        __syncthreads();
        if (more) {
            int ob = buf ^ 1;
            #pragma unroll
            for (int i = 0; i < 2; i++) {
                int base = (i * 64 + lrow) * SST + lc4;
                As[ob][base + 0] = __uint_as_float(f2tf32(xv[i].x));
                As[ob][base + 1] = __uint_as_float(f2tf32(xv[i].y));
                As[ob][base + 2] = __uint_as_float(f2tf32(xv[i].z));
                As[ob][base + 3] = __uint_as_float(f2tf32(xv[i].w));
                Bs[ob][base + 0] = __uint_as_float(f2tf32(wv[i].x));
                Bs[ob][base + 1] = __uint_as_float(f2tf32(wv[i].y));
                Bs[ob][base + 2] = __uint_as_float(f2tf32(wv[i].z));
                Bs[ob][base + 3] = __uint_as_float(f2tf32(wv[i].w));
            }
            __syncthreads();
        }
    }

    #pragma unroll
    for (int mt = 0; mt < 2; mt++) {
        #pragma unroll
        for (int nt = 0; nt < 8; nt++) {
            int col = n0 + wn + nt * 8 + tg * 2;
            float2 bv = *(const float2*)(bias + col);
            int r0 = m0 + wm + mt * 16 + gid;
            float2 o0 = {acc[mt][nt][0] + bv.x, acc[mt][nt][1] + bv.y};
            float2 o1 = {acc[mt][nt][2] + bv.x, acc[mt][nt][3] + bv.y};
            *(float2*)(C + (size_t)r0 * D + col)       = o0;
            *(float2*)(C + (size_t)(r0 + 8) * D + col) = o1;
        }
    }
}

// ---------------------------------------------------------------------------
// out[row,:] = act( P[row,:] + sum_{c in A} XA[c,:] + sum_{c in B} XB[c,:] )
// float4-vectorized: 64 threads per row, 4 rows per 256-thread block.
// Per-column summation order identical to the scalar version.
// ---------------------------------------------------------------------------
__global__ void __launch_bounds__(256) combine4_kernel(
    const float* __restrict__ P,
    const float* __restrict__ XA,
    const float* __restrict__ XB,
    int matA, int matB,
    float* __restrict__ out,
    int do_norm)
{
    __shared__ int sA[4][MAXNNZ];
    __shared__ int sB[4][MAXNNZ];
    __shared__ float red[4][2];

    int tid = threadIdx.x;
    int r   = tid >> 6;              // row slot 0..3
    int t   = tid & 63;              // 0..63
    int row = blockIdx.x * 4 + r;

    int lenA = g_len[matA][row];
    int lenB = g_len[matB][row];
    {
        const int* cA = &g_cols[matA][row * MAXNNZ];
        const int* cB = &g_cols[matB][row * MAXNNZ];
        if (t      < lenA) sA[r][t]      = cA[t];
        if (t + 64 < lenA) sA[r][t + 64] = cA[t + 64];
        if (t      < lenB) sB[r][t]      = cB[t];
        if (t + 64 < lenB) sB[r][t + 64] = cB[t + 64];
    }
    __syncthreads();

    int c4 = t * 4;
    float4 acc = *(const float4*)(P + (size_t)row * D + c4);
    #pragma unroll 4
    for (int i = 0; i < lenA; i++) {
        float4 v = *(const float4*)(XA + (size_t)sA[r][i] * D + c4);
        acc.x += v.x; acc.y += v.y; acc.z += v.z; acc.w += v.w;
    }
    #pragma unroll 4
    for (int i = 0; i < lenB; i++) {
        float4 v = *(const float4*)(XB + (size_t)sB[r][i] * D + c4);
        acc.x += v.x; acc.y += v.y; acc.z += v.z; acc.w += v.w;
    }
    acc.x = acc.x > 0.0f ? acc.x : 0.1f * acc.x;
    acc.y = acc.y > 0.0f ? acc.y : 0.1f * acc.y;
    acc.z = acc.z > 0.0f ? acc.z : 0.1f * acc.z;
    acc.w = acc.w > 0.0f ? acc.w : 0.1f * acc.w;

    if (do_norm) {
        float s = acc.x * acc.x + acc.y * acc.y + acc.z * acc.z + acc.w * acc.w;
        #pragma unroll
        for (int off = 16; off > 0; off >>= 1)
            s += __shfl_xor_sync(0xffffffffu, s, off);
        if ((t & 31) == 0) red[r][t >> 5] = s;
        __syncthreads();
        float inv = 1.0f / (sqrtf(red[r][0] + red[r][1]) + 1e-9f);
        acc.x *= inv; acc.y *= inv; acc.z *= inv; acc.w *= inv;
    }
    *(float4*)(out + (size_t)row * D + c4) = acc;
}

// ---------------------------------------------------------------------------
extern "C" void kernel_launch(void* const* d_in, const int* in_sizes, int n_in,
                              void* d_out, int out_size)
{
    const float* hp         = (const float*)d_in[0];
    const float* hq         = (const float*)d_in[1];
    const float* a_cons     = (const float*)d_in[2];
    const float* a_prod     = (const float*)d_in[3];
    const float* a_rev_cons = (const float*)d_in[4];
    const float* a_rev_prod = (const float*)d_in[5];
    const float* w[12];
    const float* b[12];
    for (int i = 0; i < 12; i++) {
        w[i] = (const float*)d_in[6 + 2 * i];
        b[i] = (const float*)d_in[7 + 2 * i];
    }
    float* out = (float*)d_out;

    void* symp = nullptr;
    cudaGetSymbolAddress(&symp, g_buf);
    float* B0 = (float*)symp;
    #define BUF(i) (B0 + (size_t)(i) * N_NODES * D)

    dim3 gg(12, N_NODES / 128), gb(256);

    // adjacency ELL: 0=a_cons, 1=a_prod, 2=a_rev_cons, 3=a_rev_prod.
    // Extract is independent of the layer-1 GEMMs; run it on a side stream so
    // its 1 GB DRAM read hides under the tensor-core work.
    bool fork = (g_sinit && g_s2);
    if (fork) {
        cudaEventRecord(g_evF, 0);
        cudaStreamWaitEvent(g_s2, g_evF, 0);
        extract_kernel<<<4 * N_NODES / 8, 256, 0, g_s2>>>(a_cons, a_prod, a_rev_cons, a_rev_prod);
        cudaEventRecord(g_evJ, g_s2);
    } else {
        extract_kernel<<<4 * N_NODES / 8, 256>>>(a_cons, a_prod, a_rev_cons, a_rev_prod);
    }

    // ---- layer 1 (K = 512) ----
    // P-side (mats 0..2): X=hp -> {wp1->BUF0, wprod1->BUF4, wrcons1->BUF5}
    // Q-side (mats 3..5): X=hq -> {wq1->BUF1, wcons1->BUF2, wrprod1->BUF3}
    gemm6_mma<<<gg, gb>>>(hp, hq,
                          w[0], w[4], w[5], w[1], w[2], w[3],
                          b[0], b[4], b[5], b[1], b[2], b[3],
                          BUF(0), BUF(4), BUF(5), BUF(1), BUF(2), BUF(3), 512);
    if (fork) cudaStreamWaitEvent(0, g_evJ, 0);
    combine4_kernel<<<N_NODES / 4, 256>>>(BUF(0), BUF(2), BUF(3), 0, 3, BUF(6), 0);  // hp1
    combine4_kernel<<<N_NODES / 4, 256>>>(BUF(1), BUF(4), BUF(5), 1, 2, BUF(7), 0);  // hq1

    // ---- layer 2 (K = 256) ----
    gemm6_mma<<<gg, gb>>>(BUF(6), BUF(7),
                          w[6], w[10], w[11], w[7], w[8], w[9],
                          b[6], b[10], b[11], b[7], b[8], b[9],
                          BUF(0), BUF(4), BUF(5), BUF(1), BUF(2), BUF(3), 256);
    combine4_kernel<<<N_NODES / 4, 256>>>(BUF(0), BUF(2), BUF(3), 0, 3, out, 1);
    combine4_kernel<<<N_NODES / 4, 256>>>(BUF(1), BUF(4), BUF(5), 1, 2, out + (size_t)N_NODES * D, 1);
    #undef BUF
}